// round 2
// baseline (speedup 1.0000x reference)
#include <cuda_runtime.h>

// Shapes (fixed by the problem)
#define Dd 1024
#define Tt 32
#define Bb 16
#define Ss 128
#define TG 4           // t-values per attn CTA

// Scratch for the two projection GEMMs (allocation-free rule: __device__ globals)
__device__ float g_pi[Tt * Bb * Dd];   // [T*B, D]  pi = inputs @ W_in^T + b_in
__device__ float g_pc[Bb * Ss * Dd];   // [B*S, D]  pc = context @ W_ctx^T + b_ctx

// ---------------------------------------------------------------------------
// Packed f32x2 helpers (Blackwell FFMA2 path — only reachable via PTX)
// ---------------------------------------------------------------------------
__device__ __forceinline__ void ffma2(unsigned long long& d,
                                      unsigned long long a,
                                      unsigned long long b) {
    asm("fma.rn.f32x2 %0, %1, %2, %0;" : "+l"(d) : "l"(a), "l"(b));
}
__device__ __forceinline__ float2 unpack2(unsigned long long v) {
    float2 f;
    asm("mov.b64 {%0, %1}, %2;" : "=f"(f.x), "=f"(f.y) : "l"(v));
    return f;
}

// ---------------------------------------------------------------------------
// GEMM: C[m,n] = sum_k A[m,k] * W[n,k] + bias[n]   (row-major NT gemm)
// Fused grid: blocks [0,64) -> pi (M=512), blocks [64,320) -> pc (M=2048).
// BM=128, BN=64, BK=16, 256 threads.
// Microtile per thread: 8 rows x 4 cols, computed as 4 row-PAIRS x 4 cols of
// FFMA2.  A-pairs are adjacent rows in transposed smem (direct 64-bit loads);
// B is stored DUPLICATED in smem so b-dup pairs also load directly.
// Inner loop: 4 x LDS.128 + 16 x FFMA2 per kk -> 128 MAC-lanes/cyc/SM.
// ---------------------------------------------------------------------------
#define BM 128
#define BN 64
#define BK 16

__global__ void __launch_bounds__(256) gemm_kernel(
    const float* __restrict__ inputs, const float* __restrict__ context,
    const float* __restrict__ W_in,  const float* __restrict__ b_in,
    const float* __restrict__ W_ctx, const float* __restrict__ b_ctx)
{
    const float* A; const float* W; const float* bias; float* Cout;
    int tile;
    if (blockIdx.x < 64) { A = inputs;  W = W_in;  bias = b_in;  Cout = g_pi; tile = blockIdx.x; }
    else                 { A = context; W = W_ctx; bias = b_ctx; Cout = g_pc; tile = blockIdx.x - 64; }
    const int bm = (tile >> 4) * BM;   // 16 N-tiles of 64 across D=1024
    const int bn = (tile & 15) * BN;

    __shared__ __align__(16) float As [BK][BM + 4];       // transposed A tile
    __shared__ __align__(16) float Bs2[BK][2 * BN + 8];   // transposed W tile, each value DUPLICATED

    const int tid = threadIdx.x;
    const int ar  = tid >> 2;          // 0..63
    const int ac4 = tid & 3;           // float4 column group within BK=16

    const float* aP0 = A + (size_t)(bm + ar) * Dd + ac4 * 4;
    const float* aP1 = aP0 + 64 * Dd;
    const float* bP  = W + (size_t)(bn + ar) * Dd + ac4 * 4;

    const int tx = tid & 15;           // 4 output cols: bn + tx*4 ..
    const int ty = tid >> 4;           // 8 output rows: bm + ty*8 ..

    unsigned long long acc2[4][4];     // [row-pair][col], f32x2 packed (lo=even row)
    #pragma unroll
    for (int i = 0; i < 4; i++)
        #pragma unroll
        for (int j = 0; j < 4; j++) acc2[i][j] = 0ull;

    float4 a0 = *(const float4*)aP0;
    float4 a1 = *(const float4*)aP1;
    float4 b0 = *(const float4*)bP;

    for (int k0 = 0; k0 < Dd; k0 += BK) {
        // store current tile (transposed) to smem; B duplicated
        As[ac4*4+0][ar]    = a0.x;  As[ac4*4+1][ar]    = a0.y;
        As[ac4*4+2][ar]    = a0.z;  As[ac4*4+3][ar]    = a0.w;
        As[ac4*4+0][ar+64] = a1.x;  As[ac4*4+1][ar+64] = a1.y;
        As[ac4*4+2][ar+64] = a1.z;  As[ac4*4+3][ar+64] = a1.w;
        Bs2[ac4*4+0][2*ar] = b0.x;  Bs2[ac4*4+0][2*ar+1] = b0.x;
        Bs2[ac4*4+1][2*ar] = b0.y;  Bs2[ac4*4+1][2*ar+1] = b0.y;
        Bs2[ac4*4+2][2*ar] = b0.z;  Bs2[ac4*4+2][2*ar+1] = b0.z;
        Bs2[ac4*4+3][2*ar] = b0.w;  Bs2[ac4*4+3][2*ar+1] = b0.w;
        __syncthreads();

        // prefetch next tile into registers (overlaps with compute below)
        if (k0 + BK < Dd) {
            a0 = *(const float4*)(aP0 + k0 + BK);
            a1 = *(const float4*)(aP1 + k0 + BK);
            b0 = *(const float4*)(bP  + k0 + BK);
        }

        #pragma unroll
        for (int kk = 0; kk < BK; kk++) {
            // a row-pairs: (r0,r1),(r2,r3),(r4,r5),(r6,r7) of this thread's 8 rows
            ulonglong2 aA = *(const ulonglong2*)&As[kk][ty * 8];
            ulonglong2 aB = *(const ulonglong2*)&As[kk][ty * 8 + 4];
            // b duplicated pairs: (b0,b0),(b1,b1),(b2,b2),(b3,b3)
            ulonglong2 bA = *(const ulonglong2*)&Bs2[kk][tx * 8];
            ulonglong2 bB = *(const ulonglong2*)&Bs2[kk][tx * 8 + 4];

            ffma2(acc2[0][0], aA.x, bA.x); ffma2(acc2[0][1], aA.x, bA.y);
            ffma2(acc2[0][2], aA.x, bB.x); ffma2(acc2[0][3], aA.x, bB.y);
            ffma2(acc2[1][0], aA.y, bA.x); ffma2(acc2[1][1], aA.y, bA.y);
            ffma2(acc2[1][2], aA.y, bB.x); ffma2(acc2[1][3], aA.y, bB.y);
            ffma2(acc2[2][0], aB.x, bA.x); ffma2(acc2[2][1], aB.x, bA.y);
            ffma2(acc2[2][2], aB.x, bB.x); ffma2(acc2[2][3], aB.x, bB.y);
            ffma2(acc2[3][0], aB.y, bA.x); ffma2(acc2[3][1], aB.y, bA.y);
            ffma2(acc2[3][2], aB.y, bB.x); ffma2(acc2[3][3], aB.y, bB.y);
        }
        __syncthreads();
    }

    const float4 bv = *(const float4*)(bias + bn + tx * 4);
    #pragma unroll
    for (int i2 = 0; i2 < 4; i2++) {
        float2 c0 = unpack2(acc2[i2][0]);
        float2 c1 = unpack2(acc2[i2][1]);
        float2 c2 = unpack2(acc2[i2][2]);
        float2 c3 = unpack2(acc2[i2][3]);
        float4 lo, hi;
        lo.x = c0.x + bv.x; lo.y = c1.x + bv.y; lo.z = c2.x + bv.z; lo.w = c3.x + bv.w;
        hi.x = c0.y + bv.x; hi.y = c1.y + bv.y; hi.z = c2.y + bv.z; hi.w = c3.y + bv.w;
        float* base = Cout + (size_t)(bm + ty * 8 + 2 * i2) * Dd + bn + tx * 4;
        *(float4*)base        = lo;
        *(float4*)(base + Dd) = hi;
    }
}

// ---------------------------------------------------------------------------
// Fused scores -> softmax -> weighted context sum, TG=4 t-values per CTA.
// grid = B * (T/TG) = 128 CTAs, 256 threads.
// Swish via tanh.approx (1 MUFU/element): swish(c) = h + h*tanh(h), h = c/2.
// b_one omitted: softmax is shift-invariant.
// ---------------------------------------------------------------------------
#define SWISH_ACC(accv, pic, pcc, wc)                                    \
    {                                                                    \
        float c_ = (pic) + (pcc);                                        \
        float h_ = 0.5f * c_;                                            \
        float th_;                                                       \
        asm("tanh.approx.f32 %0, %1;" : "=f"(th_) : "f"(h_));            \
        (accv) = fmaf(fmaf(th_, h_, h_), (wc), (accv));                  \
    }

__global__ void __launch_bounds__(256) attn_kernel(
    const float* __restrict__ context,
    const float* __restrict__ w_one,
    float* __restrict__ out)   // [0,T*B*D): attn_context ; [T*B*D, +T*B*S): attn
{
    const int b  = blockIdx.x & (Bb - 1);
    const int tg = blockIdx.x >> 4;          // t-group: t = tg*TG + tt

    __shared__ __align__(16) float4 s_pi[TG][Dd / 4];
    __shared__ __align__(16) float4 s_w[Dd / 4];
    __shared__ float s_sc[TG][Ss];

    const int tid  = threadIdx.x;
    const int lane = tid & 31;
    const int warp = tid >> 5;

    s_w[tid] = ((const float4*)w_one)[tid];
    #pragma unroll
    for (int tt = 0; tt < TG; tt++) {
        const int tb = (tg * TG + tt) * Bb + b;
        s_pi[tt][tid] = ((const float4*)(g_pi + (size_t)tb * Dd))[tid];
    }
    __syncthreads();

    // ---- scores[tt][s] = sum_d swish(pi[tt,d] + pc[s,d]) * w[d] ----
    const float* pcb = g_pc + (size_t)b * Ss * Dd;
    for (int s = warp; s < Ss; s += 8) {
        const float4* row = (const float4*)(pcb + (size_t)s * Dd);
        float acc[TG] = {0.f, 0.f, 0.f, 0.f};
        #pragma unroll
        for (int i = 0; i < 8; i++) {
            const int idx = i * 32 + lane;
            const float4 pcv = row[idx];
            const float4 wv  = s_w[idx];
            #pragma unroll
            for (int tt = 0; tt < TG; tt++) {
                const float4 piv = s_pi[tt][idx];
                SWISH_ACC(acc[tt], piv.x, pcv.x, wv.x);
                SWISH_ACC(acc[tt], piv.y, pcv.y, wv.y);
                SWISH_ACC(acc[tt], piv.z, pcv.z, wv.z);
                SWISH_ACC(acc[tt], piv.w, pcv.w, wv.w);
            }
        }
        #pragma unroll
        for (int tt = 0; tt < TG; tt++) {
            float a = acc[tt];
            #pragma unroll
            for (int o = 16; o > 0; o >>= 1)
                a += __shfl_xor_sync(0xffffffffu, a, o);
            if (lane == 0) s_sc[tt][s] = a;
        }
    }
    __syncthreads();

    // ---- softmax: warp tt handles row tt (4 values per lane, stride 32) ----
    if (warp < TG) {
        const int tt = warp;
        float v0 = s_sc[tt][lane];
        float v1 = s_sc[tt][lane + 32];
        float v2 = s_sc[tt][lane + 64];
        float v3 = s_sc[tt][lane + 96];
        float m = fmaxf(fmaxf(v0, v1), fmaxf(v2, v3));
        #pragma unroll
        for (int o = 16; o > 0; o >>= 1)
            m = fmaxf(m, __shfl_xor_sync(0xffffffffu, m, o));
        float p0 = __expf(v0 - m), p1 = __expf(v1 - m);
        float p2 = __expf(v2 - m), p3 = __expf(v3 - m);
        float sum = p0 + p1 + p2 + p3;
        #pragma unroll
        for (int o = 16; o > 0; o >>= 1)
            sum += __shfl_xor_sync(0xffffffffu, sum, o);
        const float inv = __fdividef(1.f, sum);
        const int tb = (tg * TG + tt) * Bb + b;
        float* attn_out = out + (size_t)Tt * Bb * Dd + (size_t)tb * Ss;
        p0 *= inv; p1 *= inv; p2 *= inv; p3 *= inv;
        s_sc[tt][lane]      = p0;  attn_out[lane]      = p0;
        s_sc[tt][lane + 32] = p1;  attn_out[lane + 32] = p1;
        s_sc[tt][lane + 64] = p2;  attn_out[lane + 64] = p2;
        s_sc[tt][lane + 96] = p3;  attn_out[lane + 96] = p3;
    }
    __syncthreads();

    // ---- attn_context[t,b,:] = sum_s attn[t,s] * context[b,s,:] ----
    // Each thread owns one float4 column chunk; context loaded ONCE for all TG t's.
    const float4* ctx4 = (const float4*)(context + (size_t)b * Ss * Dd);
    float4 acc[TG];
    #pragma unroll
    for (int tt = 0; tt < TG; tt++) acc[tt] = make_float4(0.f, 0.f, 0.f, 0.f);

    #pragma unroll 4
    for (int s = 0; s < Ss; s++) {
        const float4 c = ctx4[(size_t)s * (Dd / 4) + tid];
        #pragma unroll
        for (int tt = 0; tt < TG; tt++) {
            const float a = s_sc[tt][s];
            acc[tt].x = fmaf(a, c.x, acc[tt].x);
            acc[tt].y = fmaf(a, c.y, acc[tt].y);
            acc[tt].z = fmaf(a, c.z, acc[tt].z);
            acc[tt].w = fmaf(a, c.w, acc[tt].w);
        }
    }
    #pragma unroll
    for (int tt = 0; tt < TG; tt++) {
        const int tb = (tg * TG + tt) * Bb + b;
        ((float4*)(out + (size_t)tb * Dd))[tid] = acc[tt];
    }
}

// ---------------------------------------------------------------------------
extern "C" void kernel_launch(void* const* d_in, const int* in_sizes, int n_in,
                              void* d_out, int out_size) {
    const float* inputs  = (const float*)d_in[0];
    const float* context = (const float*)d_in[1];
    const float* W_in    = (const float*)d_in[2];
    const float* b_in    = (const float*)d_in[3];
    const float* W_ctx   = (const float*)d_in[4];
    const float* b_ctx   = (const float*)d_in[5];
    const float* w_one   = (const float*)d_in[6];
    // d_in[7] = b_one: softmax is shift-invariant -> no effect on either output.
    float* out = (float*)d_out;

    gemm_kernel<<<320, 256>>>(inputs, context, W_in, b_in, W_ctx, b_ctx);
    attn_kernel<<<Bb * (Tt / TG), 256>>>(context, w_one, out);
}

// round 5
// speedup vs baseline: 3.0777x; 3.0777x over previous
#include <cuda_runtime.h>
#include <cstdint>

// Shapes (fixed by the problem)
#define Dd 1024
#define Tt 32
#define Bb 16
#define Ss 128
#define TG 4

// Scratch for the two projection GEMMs
__device__ float g_pi[Tt * Bb * Dd];   // [T*B, D]
__device__ float g_pc[Bb * Ss * Dd];   // [B*S, D]

// ===========================================================================
// Helpers
// ===========================================================================
__device__ __forceinline__ uint32_t smem_to_u32(const void* p) {
    uint32_t a;
    asm("{ .reg .u64 t; cvta.to.shared.u64 t, %1; cvt.u32.u64 %0, t; }" : "=r"(a) : "l"(p));
    return a;
}
// pack two floats into bf16x2 (lo -> lower half, hi -> upper half)
__device__ __forceinline__ uint32_t pack_bf16x2(float lo, float hi) {
    uint32_t r;
    asm("cvt.rn.bf16x2.f32 %0, %1, %2;" : "=r"(r) : "f"(hi), "f"(lo));
    return r;
}
__device__ __forceinline__ void ldsm_x4(uint32_t* r, uint32_t addr) {
    asm volatile("ldmatrix.sync.aligned.m8n8.x4.shared.b16 {%0,%1,%2,%3}, [%4];"
                 : "=r"(r[0]), "=r"(r[1]), "=r"(r[2]), "=r"(r[3]) : "r"(addr));
}
__device__ __forceinline__ void mma_bf16(float* c, const uint32_t* a,
                                         uint32_t b0, uint32_t b1) {
    asm volatile(
        "mma.sync.aligned.m16n8k16.row.col.f32.bf16.bf16.f32 "
        "{%0,%1,%2,%3}, {%4,%5,%6,%7}, {%8,%9}, {%0,%1,%2,%3};"
        : "+f"(c[0]), "+f"(c[1]), "+f"(c[2]), "+f"(c[3])
        : "r"(a[0]), "r"(a[1]), "r"(a[2]), "r"(a[3]), "r"(b0), "r"(b1));
}

// ===========================================================================
// bf16 3-MMA split GEMM:  C[m,n] = sum_k A[m,k]*W[n,k] + bias[n]
//   x = hi(bf16) + lo(bf16);  C ≈ Ah*Bh + Al*Bh + Ah*Bl  (fp32 accum)
// BM=128, BN=64, KC=32. 256 threads = 8 warps in 4(m) x 2(n); warp tile 32x32.
// smem: bf16 planes Ah/Al (128 x 32, pitch 80B) and Bh/Bl (64 x 32, pitch 80B).
// Grid: blocks [0,64) -> pi (M=512), [64,320) -> pc (M=2048).
// ===========================================================================
#define BMt 128
#define BNt 64
#define KC  32
#define NCHUNK (Dd / KC)        // 32
#define PITCH 80                // bytes per bf16 row (32 bf16 = 64B + 16B pad)

__global__ void __launch_bounds__(256) gemm_kernel(
    const float* __restrict__ inputs, const float* __restrict__ context,
    const float* __restrict__ W_in,  const float* __restrict__ b_in,
    const float* __restrict__ W_ctx, const float* __restrict__ b_ctx)
{
    __shared__ __align__(16) char sAh[BMt * PITCH];   // 10240 B
    __shared__ __align__(16) char sAl[BMt * PITCH];
    __shared__ __align__(16) char sBh[BNt * PITCH];   //  5120 B
    __shared__ __align__(16) char sBl[BNt * PITCH];

    const int tid  = threadIdx.x;
    const int wid  = tid >> 5;
    const int lane = tid & 31;

    const float* A; const float* W; const float* bias; float* Cout; int tile;
    if (blockIdx.x < 64) { A = inputs;  W = W_in;  bias = b_in;  Cout = g_pi; tile = blockIdx.x; }
    else                 { A = context; W = W_ctx; bias = b_ctx; Cout = g_pc; tile = blockIdx.x - 64; }
    const int bm = (tile >> 4) * BMt;   // 16 N-tiles of 64 over D=1024
    const int bn = (tile & 15) * BNt;

    const int warp_m = wid & 3;         // 0..3 -> m offset 32*warp_m
    const int warp_n = wid >> 2;        // 0..1 -> n offset 32*warp_n

    // ---- per-thread gmem slots (float4): A: 4, B: 2 ----
    float4 ra[4], rb[2];
    #pragma unroll
    for (int i = 0; i < 4; i++) {
        const int e = i * 256 + tid;                 // row = e>>3, c4 = e&7
        ra[i] = *(const float4*)(A + (size_t)(bm + (e >> 3)) * Dd + (e & 7) * 4);
    }
    #pragma unroll
    for (int i = 0; i < 2; i++) {
        const int e = i * 256 + tid;
        rb[i] = *(const float4*)(W + (size_t)(bn + (e >> 3)) * Dd + (e & 7) * 4);
    }

    // ---- ldmatrix lane address offsets ----
    const int lr  = lane & 7;
    const int grp = lane >> 3;          // 0..3
    // A tiles: t0:(m+lr,k0) t1:(m+8+lr,k0) t2:(m+lr,k8) t3:(m+8+lr,k8)
    const uint32_t aRowOff = (uint32_t)((warp_m * 32 + (grp & 1) * 8 + lr) * PITCH
                                        + (grp >> 1) * 16);
    // B tiles: t0:(n+lr,k0) t1:(n+lr,k8) t2:(n+8+lr,k0) t3:(n+8+lr,k8)
    const uint32_t bRowOff = (uint32_t)((warp_n * 32 + (grp >> 1) * 8 + lr) * PITCH
                                        + (grp & 1) * 16);
    const uint32_t aAh = smem_to_u32(sAh) + aRowOff;
    const uint32_t aAl = smem_to_u32(sAl) + aRowOff;
    const uint32_t aBh = smem_to_u32(sBh) + bRowOff;
    const uint32_t aBl = smem_to_u32(sBl) + bRowOff;

    float acc[2][4][4];                 // [mi][ni][frag]
    #pragma unroll
    for (int mi = 0; mi < 2; mi++)
        #pragma unroll
        for (int ni = 0; ni < 4; ni++)
            #pragma unroll
            for (int j = 0; j < 4; j++) acc[mi][ni][j] = 0.f;

    for (int c = 0; c < NCHUNK; c++) {
        // ---- split-convert and store current chunk to smem ----
        #pragma unroll
        for (int i = 0; i < 4; i++) {
            const int e = i * 256 + tid;
            const uint32_t off = (uint32_t)((e >> 3) * PITCH + (e & 7) * 8);
            float4 v = ra[i];
            uint32_t h01 = pack_bf16x2(v.x, v.y);
            uint32_t h23 = pack_bf16x2(v.z, v.w);
            float hx = __uint_as_float(h01 << 16);
            float hy = __uint_as_float(h01 & 0xffff0000u);
            float hz = __uint_as_float(h23 << 16);
            float hw = __uint_as_float(h23 & 0xffff0000u);
            uint32_t l01 = pack_bf16x2(v.x - hx, v.y - hy);
            uint32_t l23 = pack_bf16x2(v.z - hz, v.w - hw);
            *(uint2*)(sAh + off) = make_uint2(h01, h23);
            *(uint2*)(sAl + off) = make_uint2(l01, l23);
        }
        #pragma unroll
        for (int i = 0; i < 2; i++) {
            const int e = i * 256 + tid;
            const uint32_t off = (uint32_t)((e >> 3) * PITCH + (e & 7) * 8);
            float4 v = rb[i];
            uint32_t h01 = pack_bf16x2(v.x, v.y);
            uint32_t h23 = pack_bf16x2(v.z, v.w);
            float hx = __uint_as_float(h01 << 16);
            float hy = __uint_as_float(h01 & 0xffff0000u);
            float hz = __uint_as_float(h23 << 16);
            float hw = __uint_as_float(h23 & 0xffff0000u);
            uint32_t l01 = pack_bf16x2(v.x - hx, v.y - hy);
            uint32_t l23 = pack_bf16x2(v.z - hz, v.w - hw);
            *(uint2*)(sBh + off) = make_uint2(h01, h23);
            *(uint2*)(sBl + off) = make_uint2(l01, l23);
        }
        __syncthreads();

        // ---- prefetch next chunk (overlaps with MMA below) ----
        if (c + 1 < NCHUNK) {
            const int kb = (c + 1) * KC;
            #pragma unroll
            for (int i = 0; i < 4; i++) {
                const int e = i * 256 + tid;
                ra[i] = *(const float4*)(A + (size_t)(bm + (e >> 3)) * Dd + kb + (e & 7) * 4);
            }
            #pragma unroll
            for (int i = 0; i < 2; i++) {
                const int e = i * 256 + tid;
                rb[i] = *(const float4*)(W + (size_t)(bn + (e >> 3)) * Dd + kb + (e & 7) * 4);
            }
        }

        // ---- compute: 2 k16 steps ----
        #pragma unroll
        for (int ks = 0; ks < 2; ks++) {
            const uint32_t ko = ks * 32;    // 16 bf16 = 32 bytes
            uint32_t ah[2][4], al[2][4], bh[2][4], bl[2][4];
            #pragma unroll
            for (int mi = 0; mi < 2; mi++) {
                ldsm_x4(ah[mi], aAh + mi * 16 * PITCH + ko);
                ldsm_x4(al[mi], aAl + mi * 16 * PITCH + ko);
            }
            #pragma unroll
            for (int ng = 0; ng < 2; ng++) {
                ldsm_x4(bh[ng], aBh + ng * 16 * PITCH + ko);
                ldsm_x4(bl[ng], aBl + ng * 16 * PITCH + ko);
            }
            #pragma unroll
            for (int mi = 0; mi < 2; mi++)
                #pragma unroll
                for (int ni = 0; ni < 4; ni++) {
                    const int ng = ni >> 1, sel = (ni & 1) * 2;
                    mma_bf16(acc[mi][ni], ah[mi], bh[ng][sel], bh[ng][sel + 1]);
                    mma_bf16(acc[mi][ni], al[mi], bh[ng][sel], bh[ng][sel + 1]);
                    mma_bf16(acc[mi][ni], ah[mi], bl[ng][sel], bl[ng][sel + 1]);
                }
        }
        __syncthreads();
    }

    // ---- epilogue: bias add + store ----
    const int tq = lane >> 2;           // row within m16 tile
    const int tr = lane & 3;            // col pair
    #pragma unroll
    for (int mi = 0; mi < 2; mi++)
        #pragma unroll
        for (int ni = 0; ni < 4; ni++) {
            const int col  = bn + warp_n * 32 + ni * 8 + tr * 2;
            const int row0 = bm + warp_m * 32 + mi * 16 + tq;
            const float2 bv = *(const float2*)(bias + col);
            float2 o0, o1;
            o0.x = acc[mi][ni][0] + bv.x;  o0.y = acc[mi][ni][1] + bv.y;
            o1.x = acc[mi][ni][2] + bv.x;  o1.y = acc[mi][ni][3] + bv.y;
            *(float2*)(Cout + (size_t)row0 * Dd + col)       = o0;
            *(float2*)(Cout + (size_t)(row0 + 8) * Dd + col) = o1;
        }
}

// ===========================================================================
// Fused scores -> softmax -> weighted context sum (UNCHANGED from R2, 50us).
// ===========================================================================
#define SWISH_ACC(accv, pic, pcc, wc)                                    \
    {                                                                    \
        float c_ = (pic) + (pcc);                                        \
        float h_ = 0.5f * c_;                                            \
        float th_;                                                       \
        asm("tanh.approx.f32 %0, %1;" : "=f"(th_) : "f"(h_));            \
        (accv) = fmaf(fmaf(th_, h_, h_), (wc), (accv));                  \
    }

__global__ void __launch_bounds__(256) attn_kernel(
    const float* __restrict__ context,
    const float* __restrict__ w_one,
    float* __restrict__ out)
{
    const int b  = blockIdx.x & (Bb - 1);
    const int tg = blockIdx.x >> 4;

    __shared__ __align__(16) float4 s_pi[TG][Dd / 4];
    __shared__ __align__(16) float4 s_w[Dd / 4];
    __shared__ float s_sc[TG][Ss];

    const int tid  = threadIdx.x;
    const int lane = tid & 31;
    const int warp = tid >> 5;

    s_w[tid] = ((const float4*)w_one)[tid];
    #pragma unroll
    for (int tt = 0; tt < TG; tt++) {
        const int tb = (tg * TG + tt) * Bb + b;
        s_pi[tt][tid] = ((const float4*)(g_pi + (size_t)tb * Dd))[tid];
    }
    __syncthreads();

    const float* pcb = g_pc + (size_t)b * Ss * Dd;
    for (int s = warp; s < Ss; s += 8) {
        const float4* row = (const float4*)(pcb + (size_t)s * Dd);
        float acc[TG] = {0.f, 0.f, 0.f, 0.f};
        #pragma unroll
        for (int i = 0; i < 8; i++) {
            const int idx = i * 32 + lane;
            const float4 pcv = row[idx];
            const float4 wv  = s_w[idx];
            #pragma unroll
            for (int tt = 0; tt < TG; tt++) {
                const float4 piv = s_pi[tt][idx];
                SWISH_ACC(acc[tt], piv.x, pcv.x, wv.x);
                SWISH_ACC(acc[tt], piv.y, pcv.y, wv.y);
                SWISH_ACC(acc[tt], piv.z, pcv.z, wv.z);
                SWISH_ACC(acc[tt], piv.w, pcv.w, wv.w);
            }
        }
        #pragma unroll
        for (int tt = 0; tt < TG; tt++) {
            float a = acc[tt];
            #pragma unroll
            for (int o = 16; o > 0; o >>= 1)
                a += __shfl_xor_sync(0xffffffffu, a, o);
            if (lane == 0) s_sc[tt][s] = a;
        }
    }
    __syncthreads();

    if (warp < TG) {
        const int tt = warp;
        float v0 = s_sc[tt][lane];
        float v1 = s_sc[tt][lane + 32];
        float v2 = s_sc[tt][lane + 64];
        float v3 = s_sc[tt][lane + 96];
        float m = fmaxf(fmaxf(v0, v1), fmaxf(v2, v3));
        #pragma unroll
        for (int o = 16; o > 0; o >>= 1)
            m = fmaxf(m, __shfl_xor_sync(0xffffffffu, m, o));
        float p0 = __expf(v0 - m), p1 = __expf(v1 - m);
        float p2 = __expf(v2 - m), p3 = __expf(v3 - m);
        float sum = p0 + p1 + p2 + p3;
        #pragma unroll
        for (int o = 16; o > 0; o >>= 1)
            sum += __shfl_xor_sync(0xffffffffu, sum, o);
        const float inv = __fdividef(1.f, sum);
        const int tb = (tg * TG + tt) * Bb + b;
        float* attn_out = out + (size_t)Tt * Bb * Dd + (size_t)tb * Ss;
        p0 *= inv; p1 *= inv; p2 *= inv; p3 *= inv;
        s_sc[tt][lane]      = p0;  attn_out[lane]      = p0;
        s_sc[tt][lane + 32] = p1;  attn_out[lane + 32] = p1;
        s_sc[tt][lane + 64] = p2;  attn_out[lane + 64] = p2;
        s_sc[tt][lane + 96] = p3;  attn_out[lane + 96] = p3;
    }
    __syncthreads();

    const float4* ctx4 = (const float4*)(context + (size_t)b * Ss * Dd);
    float4 acc[TG];
    #pragma unroll
    for (int tt = 0; tt < TG; tt++) acc[tt] = make_float4(0.f, 0.f, 0.f, 0.f);

    #pragma unroll 4
    for (int s = 0; s < Ss; s++) {
        const float4 c = ctx4[(size_t)s * (Dd / 4) + tid];
        #pragma unroll
        for (int tt = 0; tt < TG; tt++) {
            const float a = s_sc[tt][s];
            acc[tt].x = fmaf(a, c.x, acc[tt].x);
            acc[tt].y = fmaf(a, c.y, acc[tt].y);
            acc[tt].z = fmaf(a, c.z, acc[tt].z);
            acc[tt].w = fmaf(a, c.w, acc[tt].w);
        }
    }
    #pragma unroll
    for (int tt = 0; tt < TG; tt++) {
        const int tb = (tg * TG + tt) * Bb + b;
        ((float4*)(out + (size_t)tb * Dd))[tid] = acc[tt];
    }
}

// ===========================================================================
extern "C" void kernel_launch(void* const* d_in, const int* in_sizes, int n_in,
                              void* d_out, int out_size) {
    const float* inputs  = (const float*)d_in[0];
    const float* context = (const float*)d_in[1];
    const float* W_in    = (const float*)d_in[2];
    const float* b_in    = (const float*)d_in[3];
    const float* W_ctx   = (const float*)d_in[4];
    const float* b_ctx   = (const float*)d_in[5];
    const float* w_one   = (const float*)d_in[6];
    // d_in[7] = b_one: softmax is shift-invariant -> no effect on outputs.
    float* out = (float*)d_out;

    gemm_kernel<<<320, 256>>>(inputs, context, W_in, b_in, W_ctx, b_ctx);
    attn_kernel<<<Bb * (Tt / TG), 256>>>(context, w_one, out);
}